// round 13
// baseline (speedup 1.0000x reference)
#include <cuda_runtime.h>
#include <cuda_fp16.h>
#include <math.h>
#include <cstdint>

#define NTOK 2048
#define DIM_ 2048
#define HID_ 7168
#define NEXP 8
#define BKH  64                 // k halves per smem tile
#define NT1  (DIM_/BKH)         // 32
#define NT2  (HID_/BKH)         // 112

#define WSZ  ((size_t)DIM_ * HID_)
#define W3OFF ((size_t)NEXP * WSZ)
#define W2OFF ((size_t)2 * NEXP * WSZ)

// ---------------- device scratch ----------------
__device__ int    g_cnt[NEXP];
__device__ int    g_tok[NEXP * NTOK];
__device__ float  g_wt [NEXP * NTOK];
__device__ __half g_act[(size_t)NTOK * 2 * HID_];
__device__ __half g_x16[(size_t)NTOK * DIM_];
__device__ __half g_w16[(size_t)3 * NEXP * WSZ];    // fp16 w1|w3|w2

// ---------------- helpers ----------------
__device__ __forceinline__ unsigned pk(float lo, float hi) {
    __half2 h = __floats2half2_rn(lo, hi);
    return *reinterpret_cast<unsigned*>(&h);
}
__device__ __forceinline__ void mma16(float* c, const unsigned* a, const unsigned* b) {
    asm volatile(
        "mma.sync.aligned.m16n8k16.row.col.f32.f16.f16.f32 "
        "{%0,%1,%2,%3}, {%4,%5,%6,%7}, {%8,%9}, {%0,%1,%2,%3};\n"
        : "+f"(c[0]), "+f"(c[1]), "+f"(c[2]), "+f"(c[3])
        : "r"(a[0]), "r"(a[1]), "r"(a[2]), "r"(a[3]), "r"(b[0]), "r"(b[1]));
}

#define LDSM(d0,d1,d2,d3,ad) asm volatile( \
    "ldmatrix.sync.aligned.m8n8.x4.shared.b16 {%0,%1,%2,%3}, [%4];" \
    : "=r"(d0),"=r"(d1),"=r"(d2),"=r"(d3) : "r"(ad))
#define LDSMT(d0,d1,d2,d3,ad) asm volatile( \
    "ldmatrix.sync.aligned.m8n8.x4.trans.shared.b16 {%0,%1,%2,%3}, [%4];" \
    : "=r"(d0),"=r"(d1),"=r"(d2),"=r"(d3) : "r"(ad))
#define CPA16(dst,src) asm volatile( \
    "cp.async.cg.shared.global [%0], [%1], 16;" :: "r"(dst), "l"(src) : "memory")
#define CPCOMMIT() asm volatile("cp.async.commit_group;" ::: "memory")
#define CPWAIT0()  asm volatile("cp.async.wait_group 0;" ::: "memory")

// A tile frag addr: 128B rows, swizzle chunk ^= (m&7)
__device__ __forceinline__ uint32_t a_addr(uint32_t aB, int mbase, int ko, int lane) {
    int m  = mbase + (lane & 7) + ((lane >> 3) & 1) * 8;
    int cb = 2 * ko + ((lane >> 4) << 4);
    return aB + m * 128 + (cb ^ ((m & 7) << 4));
}
// B tile frag addr (trans): row k, swizzle chunk ^= (k&7)
__device__ __forceinline__ uint32_t b_addr(uint32_t bB, int nbase, int ko, int lane, int stride) {
    int k  = ko + ((lane >> 3) & 1) * 8 + (lane & 7);
    int nb = nbase + ((lane >> 4) << 3);
    return bB + k * stride + ((2 * nb) ^ ((k & 7) << 4));
}

// ---------------- conversion ----------------
__global__ void cvt_w_kernel(const float* __restrict__ src, size_t dst_off) {
    size_t i = ((size_t)blockIdx.x * blockDim.x + threadIdx.x) * 8;
    float4 v0 = *reinterpret_cast<const float4*>(src + i);
    float4 v1 = *reinterpret_cast<const float4*>(src + i + 4);
    uint4 u;
    u.x = pk(v0.x, v0.y); u.y = pk(v0.z, v0.w);
    u.z = pk(v1.x, v1.y); u.w = pk(v1.z, v1.w);
    *reinterpret_cast<uint4*>(&g_w16[dst_off + i]) = u;
}

__global__ void zero_cnt_kernel() {
    if (threadIdx.x < NEXP) g_cnt[threadIdx.x] = 0;
}

// gate + fused x fp16 conversion
__global__ __launch_bounds__(128) void gate_kernel(const float* __restrict__ x,
                                                   const float* __restrict__ Wg) {
    __shared__ float red[128 * NEXP];
    __shared__ float sc[NEXP];
    int t = blockIdx.x;
    const float* xr = x + (size_t)t * DIM_;
    __half* xo = g_x16 + (size_t)t * DIM_;
    float acc[NEXP];
#pragma unroll
    for (int e = 0; e < NEXP; e++) acc[e] = 0.f;
    for (int i = threadIdx.x; i < DIM_; i += 128) {
        float xv = xr[i];
        xo[i] = __float2half_rn(xv);
        const float4* w4 = reinterpret_cast<const float4*>(Wg + (size_t)i * NEXP);
        float4 wa = w4[0], wb = w4[1];
        acc[0] += xv * wa.x; acc[1] += xv * wa.y;
        acc[2] += xv * wa.z; acc[3] += xv * wa.w;
        acc[4] += xv * wb.x; acc[5] += xv * wb.y;
        acc[6] += xv * wb.z; acc[7] += xv * wb.w;
    }
#pragma unroll
    for (int e = 0; e < NEXP; e++) red[threadIdx.x * NEXP + e] = acc[e];
    __syncthreads();
    if (threadIdx.x < NEXP) {
        int e = threadIdx.x;
        float s = 0.f;
        for (int i = 0; i < 128; i++) s += red[i * NEXP + e];
        sc[e] = s;
    }
    __syncthreads();
    if (threadIdx.x == 0) {
        int i1 = 0;
#pragma unroll
        for (int e = 1; e < NEXP; e++) if (sc[e] > sc[i1]) i1 = e;
        int i2 = (i1 == 0) ? 1 : 0;
#pragma unroll
        for (int e = 0; e < NEXP; e++) if (e != i1 && sc[e] > sc[i2]) i2 = e;
        float e2 = expf(sc[i2] - sc[i1]);
        float wa = 1.f / (1.f + e2);
        float wb = e2 / (1.f + e2);
        int s1 = atomicAdd(&g_cnt[i1], 1);
        g_tok[i1 * NTOK + s1] = t; g_wt[i1 * NTOK + s1] = wa;
        int s2 = atomicAdd(&g_cnt[i2], 1);
        g_tok[i2 * NTOK + s2] = t; g_wt[i2 * NTOK + s2] = wb;
    }
}

// ---------------- FFN1: X16 @ {w1,w3} + SwiGLU -> g_act ----------------
// 128 threads (4 warps), CTA tile 64m x 64n(per matrix), 2-stage, 4 CTAs/SM.
// smem: A 2x8KB + B1 2x8KB + B3 2x8KB = 48KB.
__global__ __launch_bounds__(128, 4) void ffn1_kernel() {
    extern __shared__ __align__(128) char smem[];
    __shared__ int toks[64];
    uint32_t sA  = (uint32_t)__cvta_generic_to_shared(smem);   // 2 x 8KB
    uint32_t sB1 = sA + 16384;                                 // 2 x 8KB
    uint32_t sB3 = sA + 32768;                                 // 2 x 8KB

    int e = blockIdx.z, cnt = g_cnt[e];
    int m0 = blockIdx.x * 64;
    if (m0 >= cnt) return;
    int n0 = blockIdx.y * 64;
    int base = 0;
#pragma unroll
    for (int i = 0; i < NEXP; i++) base += (i < e) ? g_cnt[i] : 0;
    const __half* W1 = g_w16 + (size_t)e * WSZ;
    const __half* W3 = g_w16 + W3OFF + (size_t)e * WSZ;

    int tid = threadIdx.x, lane = tid & 31, w = tid >> 5;
    if (tid < 64) {
        int m = m0 + tid;
        toks[tid] = (m < cnt) ? g_tok[e * NTOK + m] : 0;
    }
    __syncthreads();

    // loaders: 64 rows, 2 threads/row, 4 chunks each
    int ar = tid >> 1, ch0 = (tid & 1) * 4;
    const __half* asrc = g_x16 + (size_t)toks[ar] * DIM_;
    uint32_t aswz = (uint32_t)(ar & 7) << 4;
    int kb = ar;                                   // B rows = k 0..63
    uint32_t bswz = aswz;

    // 4 warps: 2m x 2n, warp tile 32m x 32n per matrix
    int wm = (w >> 1) * 32, wn = (w & 1) * 32;
    int r = lane >> 2, q = lane & 3;

    float c1[2][4][4], c3[2][4][4];
#pragma unroll
    for (int i = 0; i < 2; i++)
#pragma unroll
        for (int j = 0; j < 4; j++)
#pragma unroll
            for (int k = 0; k < 4; k++) { c1[i][j][k] = 0.f; c3[i][j][k] = 0.f; }

#define F1_CPA(K0, ST) do {                                                        \
    uint32_t a_ = sA + (ST) * 8192 + ar * 128;                                     \
    uint32_t b1_ = sB1 + (ST) * 8192 + kb * 128;                                   \
    uint32_t b3_ = sB3 + (ST) * 8192 + kb * 128;                                   \
    const __half* w1p = W1 + (size_t)((K0) + kb) * HID_ + n0;                      \
    const __half* w3p = W3 + (size_t)((K0) + kb) * HID_ + n0;                      \
    _Pragma("unroll")                                                              \
    for (int j = 0; j < 4; j++) {                                                  \
        uint32_t ch = ch0 + j;                                                     \
        CPA16(a_  + ((ch * 16) ^ aswz), asrc + (K0) + ch * 8);                     \
        CPA16(b1_ + ((ch * 16) ^ bswz), w1p + ch * 8);                             \
        CPA16(b3_ + ((ch * 16) ^ bswz), w3p + ch * 8);                             \
    }                                                                              \
    CPCOMMIT();                                                                    \
} while (0)

    F1_CPA(0, 0);

    for (int t = 0; t < NT1; t++) {
        int st = t & 1;
        CPWAIT0();
        __syncthreads();
        if (t + 1 < NT1) F1_CPA((t + 1) * BKH, st ^ 1);
        uint32_t aB = sA + st * 8192, b1B = sB1 + st * 8192, b3B = sB3 + st * 8192;
#pragma unroll
        for (int kk = 0; kk < 4; kk++) {
            int ko = kk << 4;
            unsigned a0[4], a1[4], f1[4][2], f3[4][2];
            LDSM(a0[0], a0[1], a0[2], a0[3], a_addr(aB, wm, ko, lane));
            LDSM(a1[0], a1[1], a1[2], a1[3], a_addr(aB, wm + 16, ko, lane));
            LDSMT(f1[0][0], f1[0][1], f1[1][0], f1[1][1], b_addr(b1B, wn, ko, lane, 128));
            LDSMT(f1[2][0], f1[2][1], f1[3][0], f1[3][1], b_addr(b1B, wn + 16, ko, lane, 128));
            LDSMT(f3[0][0], f3[0][1], f3[1][0], f3[1][1], b_addr(b3B, wn, ko, lane, 128));
            LDSMT(f3[2][0], f3[2][1], f3[3][0], f3[3][1], b_addr(b3B, wn + 16, ko, lane, 128));
#pragma unroll
            for (int ni = 0; ni < 4; ni++) {
                mma16(c1[0][ni], a0, f1[ni]); mma16(c1[1][ni], a1, f1[ni]);
                mma16(c3[0][ni], a0, f3[ni]); mma16(c3[1][ni], a1, f3[ni]);
            }
        }
    }

    // epilogue: SwiGLU -> g_act
#pragma unroll
    for (int mi = 0; mi < 2; mi++) {
#pragma unroll
        for (int rr = 0; rr < 2; rr++) {
            int m = m0 + wm + (mi << 4) + r + (rr << 3);
            if (m < cnt) {
                size_t rowoff = (size_t)(base + m) * HID_;
#pragma unroll
                for (int ni = 0; ni < 4; ni++) {
                    int col = n0 + wn + (ni << 3) + (q << 1);
                    float u0 = c1[mi][ni][(rr << 1)],     v0 = c3[mi][ni][(rr << 1)];
                    float u1 = c1[mi][ni][(rr << 1) + 1], v1 = c3[mi][ni][(rr << 1) + 1];
                    float h0 = (u0 / (1.f + expf(-u0))) * v0;
                    float h1 = (u1 / (1.f + expf(-u1))) * v1;
                    *reinterpret_cast<unsigned*>(&g_act[rowoff + col]) = pk(h0, h1);
                }
            }
        }
    }
}

// ---------------- FFN2: g_act @ w2 -> weighted scatter ----------------
// 128 threads (4 warps), CTA tile 64m x 128n, 2-stage, 4 CTAs/SM.
// smem: A 2x8KB + B 2x16KB = 48KB.
__global__ __launch_bounds__(128, 4) void ffn2_kernel(float* __restrict__ out) {
    extern __shared__ __align__(128) char smem[];
    uint32_t sA = (uint32_t)__cvta_generic_to_shared(smem);    // 2 x 8KB
    uint32_t sB = sA + 16384;                                  // 2 x 16KB

    int e = blockIdx.z, cnt = g_cnt[e];
    int m0 = blockIdx.x * 64;
    if (m0 >= cnt) return;
    int n0 = blockIdx.y * 128;
    int base = 0;
#pragma unroll
    for (int i = 0; i < NEXP; i++) base += (i < e) ? g_cnt[i] : 0;
    const __half* W2 = g_w16 + W2OFF + (size_t)e * WSZ;

    int tid = threadIdx.x, lane = tid & 31, w = tid >> 5;
    // A loader: 64 rows, 2 threads/row, 4 chunks
    int ar = tid >> 1, ach0 = (tid & 1) * 4;
    int arow = base + min(m0 + ar, cnt - 1);
    const __half* asrc = g_act + (size_t)arow * HID_;
    uint32_t aswz = (uint32_t)(ar & 7) << 4;
    // B loader: 64 rows x 256B (16 chunks), 2 threads/row, 8 chunks each
    int kb = ar, bch0 = (tid & 1) * 8;
    uint32_t bswz = aswz;

    // 4 warps: 2m x 2n, warp tile 32m x 64n
    int wm = (w >> 1) * 32, wn = (w & 1) * 64;
    int r = lane >> 2, q = lane & 3;

    float c[2][8][4];
#pragma unroll
    for (int i = 0; i < 2; i++)
#pragma unroll
        for (int j = 0; j < 8; j++)
#pragma unroll
            for (int k = 0; k < 4; k++) c[i][j][k] = 0.f;

#define F2_CPA(K0, ST) do {                                                        \
    uint32_t a_ = sA + (ST) * 8192 + ar * 128;                                     \
    _Pragma("unroll")                                                              \
    for (int j = 0; j < 4; j++) {                                                  \
        uint32_t ch = ach0 + j;                                                    \
        CPA16(a_ + ((ch * 16) ^ aswz), asrc + (K0) + ch * 8);                      \
    }                                                                              \
    uint32_t b_ = sB + (ST) * 16384 + kb * 256;                                    \
    const __half* wp = W2 + (size_t)((K0) + kb) * DIM_ + n0;                       \
    _Pragma("unroll")                                                              \
    for (int j = 0; j < 8; j++) {                                                  \
        uint32_t ch = bch0 + j;                                                    \
        CPA16(b_ + ((ch * 16) ^ bswz), wp + ch * 8);                               \
    }                                                                              \
    CPCOMMIT();                                                                    \
} while (0)

    F2_CPA(0, 0);

    for (int t = 0; t < NT2; t++) {
        int st = t & 1;
        CPWAIT0();
        __syncthreads();
        if (t + 1 < NT2) F2_CPA((t + 1) * BKH, st ^ 1);
        uint32_t aB = sA + st * 8192, bB = sB + st * 16384;
#pragma unroll
        for (int kk = 0; kk < 4; kk++) {
            int ko = kk << 4;
            unsigned a0[4], a1[4], bf[8][2];
            LDSM(a0[0], a0[1], a0[2], a0[3], a_addr(aB, wm, ko, lane));
            LDSM(a1[0], a1[1], a1[2], a1[3], a_addr(aB, wm + 16, ko, lane));
            LDSMT(bf[0][0], bf[0][1], bf[1][0], bf[1][1], b_addr(bB, wn,      ko, lane, 256));
            LDSMT(bf[2][0], bf[2][1], bf[3][0], bf[3][1], b_addr(bB, wn + 16, ko, lane, 256));
            LDSMT(bf[4][0], bf[4][1], bf[5][0], bf[5][1], b_addr(bB, wn + 32, ko, lane, 256));
            LDSMT(bf[6][0], bf[6][1], bf[7][0], bf[7][1], b_addr(bB, wn + 48, ko, lane, 256));
#pragma unroll
            for (int ni = 0; ni < 8; ni++) {
                mma16(c[0][ni], a0, bf[ni]);
                mma16(c[1][ni], a1, bf[ni]);
            }
        }
    }

    // epilogue: weighted scatter-add
#pragma unroll
    for (int mi = 0; mi < 2; mi++) {
#pragma unroll
        for (int rr = 0; rr < 2; rr++) {
            int m = m0 + wm + (mi << 4) + r + (rr << 3);
            if (m < cnt) {
                int tk = g_tok[e * NTOK + m];
                float wgt = g_wt[e * NTOK + m];
                float* orow = out + (size_t)tk * DIM_;
#pragma unroll
                for (int ni = 0; ni < 8; ni++) {
                    int col = n0 + wn + (ni << 3) + (q << 1);
                    atomicAdd(&orow[col],     wgt * c[mi][ni][(rr << 1)]);
                    atomicAdd(&orow[col + 1], wgt * c[mi][ni][(rr << 1) + 1]);
                }
            }
        }
    }
}

// ---------------- launch ----------------
extern "C" void kernel_launch(void* const* d_in, const int* in_sizes, int n_in,
                              void* d_out, int out_size) {
    const float* x  = (const float*)d_in[0];
    const float* Wg = (const float*)d_in[1];
    const float* w1 = (const float*)d_in[2];
    const float* w3 = (const float*)d_in[3];
    const float* w2 = (const float*)d_in[4];
    float* out = (float*)d_out;
    (void)in_sizes; (void)n_in;

    static int attr_done = 0;
    if (!attr_done) {
        cudaFuncSetAttribute(ffn1_kernel, cudaFuncAttributeMaxDynamicSharedMemorySize, 49152);
        cudaFuncSetAttribute(ffn2_kernel, cudaFuncAttributeMaxDynamicSharedMemorySize, 49152);
        attr_done = 1;
    }

    cudaMemsetAsync(out, 0, (size_t)out_size * sizeof(float), 0);
    cvt_w_kernel<<<(int)(WSZ * NEXP / (256 * 8)), 256>>>(w1, 0);
    cvt_w_kernel<<<(int)(WSZ * NEXP / (256 * 8)), 256>>>(w3, W3OFF);
    cvt_w_kernel<<<(int)(WSZ * NEXP / (256 * 8)), 256>>>(w2, W2OFF);
    zero_cnt_kernel<<<1, 32>>>();
    gate_kernel<<<NTOK, 128>>>(x, Wg);
    ffn1_kernel<<<dim3(NTOK / 64, HID_ / 64, NEXP), 128, 49152>>>();
    ffn2_kernel<<<dim3(NTOK / 64, DIM_ / 128, NEXP), 128, 49152>>>(out);
}

// round 15
// speedup vs baseline: 1.2105x; 1.2105x over previous
#include <cuda_runtime.h>
#include <cuda_fp16.h>
#include <math.h>
#include <cstdint>

#define NTOK 2048
#define DIM_ 2048
#define HID_ 7168
#define NEXP 8
#define BKH  64                 // k halves per smem tile
#define NT1  (DIM_/BKH)         // 32
#define NT2  (HID_/BKH)         // 112

#define WSZ  ((size_t)DIM_ * HID_)          // halves per expert weight matrix
#define W3OFF ((size_t)NEXP * WSZ)
#define W2OFF ((size_t)2 * NEXP * WSZ)

#define W2CHUNK 16384
#define W2NCH   ((int)(((size_t)NEXP * WSZ) / W2CHUNK))   // 7168

// ---------------- device scratch ----------------
__device__ int    g_cnt[NEXP];
__device__ int    g_w2t;                      // w2-conversion ticket counter
__device__ int    g_tok[NEXP * NTOK];
__device__ float  g_wt [NEXP * NTOK];
__device__ __half g_act[(size_t)NTOK * 2 * HID_];
__device__ __half g_x16[(size_t)NTOK * DIM_];
__device__ __half g_w16[(size_t)3 * NEXP * WSZ];    // fp16 w1|w3|w2 (704MB)

// ---------------- helpers ----------------
__device__ __forceinline__ unsigned pk(float lo, float hi) {
    __half2 h = __floats2half2_rn(lo, hi);
    return *reinterpret_cast<unsigned*>(&h);
}
__device__ __forceinline__ void mma16(float* c, const unsigned* a, const unsigned* b) {
    asm volatile(
        "mma.sync.aligned.m16n8k16.row.col.f32.f16.f16.f32 "
        "{%0,%1,%2,%3}, {%4,%5,%6,%7}, {%8,%9}, {%0,%1,%2,%3};\n"
        : "+f"(c[0]), "+f"(c[1]), "+f"(c[2]), "+f"(c[3])
        : "r"(a[0]), "r"(a[1]), "r"(a[2]), "r"(a[3]), "r"(b[0]), "r"(b[1]));
}

#define LDSM(d0,d1,d2,d3,ad) asm volatile( \
    "ldmatrix.sync.aligned.m8n8.x4.shared.b16 {%0,%1,%2,%3}, [%4];" \
    : "=r"(d0),"=r"(d1),"=r"(d2),"=r"(d3) : "r"(ad))
#define LDSMT(d0,d1,d2,d3,ad) asm volatile( \
    "ldmatrix.sync.aligned.m8n8.x4.trans.shared.b16 {%0,%1,%2,%3}, [%4];" \
    : "=r"(d0),"=r"(d1),"=r"(d2),"=r"(d3) : "r"(ad))
#define CPA16(dst,src) asm volatile( \
    "cp.async.cg.shared.global [%0], [%1], 16;" :: "r"(dst), "l"(src) : "memory")
#define CPCOMMIT() asm volatile("cp.async.commit_group;" ::: "memory")
#define CPWAIT1()  asm volatile("cp.async.wait_group 1;" ::: "memory")
#define CPWAIT0()  asm volatile("cp.async.wait_group 0;" ::: "memory")

// A tile frag addr: 128B rows, swizzle chunk ^= (m&7)
__device__ __forceinline__ uint32_t a_addr(uint32_t aB, int mbase, int ko, int lane) {
    int m  = mbase + (lane & 7) + ((lane >> 3) & 1) * 8;
    int cb = 2 * ko + ((lane >> 4) << 4);
    return aB + m * 128 + (cb ^ ((m & 7) << 4));
}
// B tile frag addr (trans): row k, swizzle chunk ^= (k&7)
__device__ __forceinline__ uint32_t b_addr(uint32_t bB, int nbase, int ko, int lane, int stride) {
    int k  = ko + ((lane >> 3) & 1) * 8 + (lane & 7);
    int nb = nbase + ((lane >> 4) << 3);
    return bB + k * stride + ((2 * nb) ^ ((k & 7) << 4));
}

// ---------------- conversion (w1/w3 only; w2 hidden inside ffn1) ----------------
__global__ void cvt_w_kernel(const float* __restrict__ src, size_t dst_off) {
    size_t i = ((size_t)blockIdx.x * blockDim.x + threadIdx.x) * 8;
    float4 v0 = *reinterpret_cast<const float4*>(src + i);
    float4 v1 = *reinterpret_cast<const float4*>(src + i + 4);
    uint4 u;
    u.x = pk(v0.x, v0.y); u.y = pk(v0.z, v0.w);
    u.z = pk(v1.x, v1.y); u.w = pk(v1.z, v1.w);
    *reinterpret_cast<uint4*>(&g_w16[dst_off + i]) = u;
}

__global__ void zero_cnt_kernel() {
    if (threadIdx.x < NEXP) g_cnt[threadIdx.x] = 0;
    if (threadIdx.x == 0)   g_w2t = 0;
}

// gate + fused x fp16 conversion
__global__ __launch_bounds__(128) void gate_kernel(const float* __restrict__ x,
                                                   const float* __restrict__ Wg) {
    __shared__ float red[128 * NEXP];
    __shared__ float sc[NEXP];
    int t = blockIdx.x;
    const float* xr = x + (size_t)t * DIM_;
    __half* xo = g_x16 + (size_t)t * DIM_;
    float acc[NEXP];
#pragma unroll
    for (int e = 0; e < NEXP; e++) acc[e] = 0.f;
    for (int i = threadIdx.x; i < DIM_; i += 128) {
        float xv = xr[i];
        xo[i] = __float2half_rn(xv);
        const float4* w4 = reinterpret_cast<const float4*>(Wg + (size_t)i * NEXP);
        float4 wa = w4[0], wb = w4[1];
        acc[0] += xv * wa.x; acc[1] += xv * wa.y;
        acc[2] += xv * wa.z; acc[3] += xv * wa.w;
        acc[4] += xv * wb.x; acc[5] += xv * wb.y;
        acc[6] += xv * wb.z; acc[7] += xv * wb.w;
    }
#pragma unroll
    for (int e = 0; e < NEXP; e++) red[threadIdx.x * NEXP + e] = acc[e];
    __syncthreads();
    if (threadIdx.x < NEXP) {
        int e = threadIdx.x;
        float s = 0.f;
        for (int i = 0; i < 128; i++) s += red[i * NEXP + e];
        sc[e] = s;
    }
    __syncthreads();
    if (threadIdx.x == 0) {
        int i1 = 0;
#pragma unroll
        for (int e = 1; e < NEXP; e++) if (sc[e] > sc[i1]) i1 = e;
        int i2 = (i1 == 0) ? 1 : 0;
#pragma unroll
        for (int e = 0; e < NEXP; e++) if (e != i1 && sc[e] > sc[i2]) i2 = e;
        float e2 = expf(sc[i2] - sc[i1]);
        float wa = 1.f / (1.f + e2);
        float wb = e2 / (1.f + e2);
        int s1 = atomicAdd(&g_cnt[i1], 1);
        g_tok[i1 * NTOK + s1] = t; g_wt[i1 * NTOK + s1] = wa;
        int s2 = atomicAdd(&g_cnt[i2], 1);
        g_tok[i2 * NTOK + s2] = t; g_wt[i2 * NTOK + s2] = wb;
    }
}

// ---------------- FFN1: X16 @ {w1,w3} + SwiGLU -> g_act ----------------
// BM=128, BN=64/matrix, BKH=64, 3-stage cp.async. smem 3x(16K+8K+8K)=96KB.
// Early-exit blocks convert w2 fp32->fp16 via BLOCK-level ticket queue.
__global__ __launch_bounds__(256, 2) void ffn1_kernel(const float* __restrict__ w2src) {
    extern __shared__ __align__(128) char smem[];
    __shared__ int toks[128];
    __shared__ int s_ticket;
    uint32_t sA  = (uint32_t)__cvta_generic_to_shared(smem);          // 3 x 16KB
    uint32_t sB1 = sA + 49152;                                        // 3 x 8KB
    uint32_t sB3 = sA + 73728;                                        // 3 x 8KB

    int e = blockIdx.z, cnt = g_cnt[e];
    int m0 = blockIdx.x * 128;
    int tid = threadIdx.x, lane = tid & 31, w = tid >> 5;

    if (m0 >= cnt) {
        // idle block: pull w2-conversion tickets (ONE ticket per BLOCK per pass)
        for (;;) {
            if (tid == 0) s_ticket = atomicAdd(&g_w2t, 1);
            __syncthreads();
            int c = s_ticket;
            __syncthreads();
            if (c >= W2NCH) return;
            size_t b0 = (size_t)c * W2CHUNK;
#pragma unroll
            for (int it = 0; it < 8; it++) {
                size_t i = b0 + (size_t)it * 2048 + (size_t)tid * 8;
                float4 v0 = *reinterpret_cast<const float4*>(w2src + i);
                float4 v1 = *reinterpret_cast<const float4*>(w2src + i + 4);
                uint4 u;
                u.x = pk(v0.x, v0.y); u.y = pk(v0.z, v0.w);
                u.z = pk(v1.x, v1.y); u.w = pk(v1.z, v1.w);
                *reinterpret_cast<uint4*>(&g_w16[W2OFF + i]) = u;
            }
        }
    }

    int n0 = blockIdx.y * 64;
    int base = 0;
#pragma unroll
    for (int i = 0; i < NEXP; i++) base += (i < e) ? g_cnt[i] : 0;
    const __half* W1 = g_w16 + (size_t)e * WSZ;
    const __half* W3 = g_w16 + W3OFF + (size_t)e * WSZ;

    if (tid < 128) {
        int m = m0 + tid;
        toks[tid] = (m < cnt) ? g_tok[e * NTOK + m] : 0;
    }
    __syncthreads();

    // loaders
    int ar = tid >> 1, ach0 = (tid & 1) * 4;         // A: row ar, 4 chunks
    const __half* asrc = g_x16 + (size_t)toks[ar] * DIM_;
    uint32_t aswz = (uint32_t)(ar & 7) << 4;
    int kb = tid >> 2, bch0 = (tid & 3) * 2;         // B: row kb, 2 chunks
    uint32_t bswz = (uint32_t)(kb & 7) << 4;

    int wm = (w >> 1) * 32, wn = (w & 1) * 32;
    int r = lane >> 2, q = lane & 3;

    float c1[2][4][4], c3[2][4][4];
#pragma unroll
    for (int i = 0; i < 2; i++)
#pragma unroll
        for (int j = 0; j < 4; j++)
#pragma unroll
            for (int k = 0; k < 4; k++) { c1[i][j][k] = 0.f; c3[i][j][k] = 0.f; }

#define F1_CPA(K0, ST) do {                                                        \
    uint32_t a_ = sA + (ST) * 16384 + ar * 128;                                    \
    _Pragma("unroll")                                                              \
    for (int j = 0; j < 4; j++) {                                                  \
        uint32_t ch = ach0 + j;                                                    \
        CPA16(a_ + ((ch * 16) ^ aswz), asrc + (K0) + ch * 8);                      \
    }                                                                              \
    uint32_t b1_ = sB1 + (ST) * 8192 + kb * 128;                                   \
    uint32_t b3_ = sB3 + (ST) * 8192 + kb * 128;                                   \
    const __half* w1p = W1 + (size_t)((K0) + kb) * HID_ + n0;                      \
    const __half* w3p = W3 + (size_t)((K0) + kb) * HID_ + n0;                      \
    _Pragma("unroll")                                                              \
    for (int j = 0; j < 2; j++) {                                                  \
        uint32_t ch = bch0 + j;                                                    \
        CPA16(b1_ + ((ch * 16) ^ bswz), w1p + ch * 8);                             \
        CPA16(b3_ + ((ch * 16) ^ bswz), w3p + ch * 8);                             \
    }                                                                              \
    CPCOMMIT();                                                                    \
} while (0)

    F1_CPA(0, 0);
    F1_CPA(BKH, 1);

    for (int t = 0; t < NT1; t++) {
        int st = t % 3;
        if (t == NT1 - 1) CPWAIT0(); else CPWAIT1();   // tail: no younger group exists
        __syncthreads();
        if (t + 2 < NT1) F1_CPA((t + 2) * BKH, (t + 2) % 3);
        uint32_t aB = sA + st * 16384, b1B = sB1 + st * 8192, b3B = sB3 + st * 8192;
#pragma unroll
        for (int kk = 0; kk < 4; kk++) {
            int ko = kk << 4;
            unsigned a0[4], a1[4], f1[4][2], f3[4][2];
            LDSM(a0[0], a0[1], a0[2], a0[3], a_addr(aB, wm, ko, lane));
            LDSM(a1[0], a1[1], a1[2], a1[3], a_addr(aB, wm + 16, ko, lane));
            LDSMT(f1[0][0], f1[0][1], f1[1][0], f1[1][1], b_addr(b1B, wn, ko, lane, 128));
            LDSMT(f1[2][0], f1[2][1], f1[3][0], f1[3][1], b_addr(b1B, wn + 16, ko, lane, 128));
            LDSMT(f3[0][0], f3[0][1], f3[1][0], f3[1][1], b_addr(b3B, wn, ko, lane, 128));
            LDSMT(f3[2][0], f3[2][1], f3[3][0], f3[3][1], b_addr(b3B, wn + 16, ko, lane, 128));
#pragma unroll
            for (int ni = 0; ni < 4; ni++) {
                mma16(c1[0][ni], a0, f1[ni]); mma16(c1[1][ni], a1, f1[ni]);
                mma16(c3[0][ni], a0, f3[ni]); mma16(c3[1][ni], a1, f3[ni]);
            }
        }
    }

    // epilogue: SwiGLU -> g_act
#pragma unroll
    for (int mi = 0; mi < 2; mi++) {
#pragma unroll
        for (int rr = 0; rr < 2; rr++) {
            int m = m0 + wm + (mi << 4) + r + (rr << 3);
            if (m < cnt) {
                size_t rowoff = (size_t)(base + m) * HID_;
#pragma unroll
                for (int ni = 0; ni < 4; ni++) {
                    int col = n0 + wn + (ni << 3) + (q << 1);
                    float u0 = c1[mi][ni][(rr << 1)],     v0 = c3[mi][ni][(rr << 1)];
                    float u1 = c1[mi][ni][(rr << 1) + 1], v1 = c3[mi][ni][(rr << 1) + 1];
                    float h0 = (u0 / (1.f + expf(-u0))) * v0;
                    float h1 = (u1 / (1.f + expf(-u1))) * v1;
                    *reinterpret_cast<unsigned*>(&g_act[rowoff + col]) = pk(h0, h1);
                }
            }
        }
    }
}

// ---------------- FFN2: g_act @ w2 -> weighted scatter ----------------
// BM=128, BN=128, BKH=64, 3-stage. smem 3x(16K+16K)=96KB.
__global__ __launch_bounds__(256, 2) void ffn2_kernel(float* __restrict__ out) {
    extern __shared__ __align__(128) char smem[];
    uint32_t sA = (uint32_t)__cvta_generic_to_shared(smem);           // 3 x 16KB
    uint32_t sB = sA + 49152;                                         // 3 x 16KB

    int e = blockIdx.z, cnt = g_cnt[e];
    int m0 = blockIdx.x * 128;
    if (m0 >= cnt) return;
    int n0 = blockIdx.y * 128;
    int base = 0;
#pragma unroll
    for (int i = 0; i < NEXP; i++) base += (i < e) ? g_cnt[i] : 0;
    const __half* W2 = g_w16 + W2OFF + (size_t)e * WSZ;

    int tid = threadIdx.x, lane = tid & 31, w = tid >> 5;
    int ar = tid >> 1, ach0 = (tid & 1) * 4;
    int arow = base + min(m0 + ar, cnt - 1);
    const __half* asrc = g_act + (size_t)arow * HID_;
    uint32_t aswz = (uint32_t)(ar & 7) << 4;
    int kb = tid >> 2, bch0 = (tid & 3) * 4;
    uint32_t bswz = (uint32_t)(kb & 7) << 4;

    int wm = (w >> 1) * 32, wn = (w & 1) * 64;
    int r = lane >> 2, q = lane & 3;

    float c[2][8][4];
#pragma unroll
    for (int i = 0; i < 2; i++)
#pragma unroll
        for (int j = 0; j < 8; j++)
#pragma unroll
            for (int k = 0; k < 4; k++) c[i][j][k] = 0.f;

#define F2_CPA(K0, ST) do {                                                        \
    uint32_t a_ = sA + (ST) * 16384 + ar * 128;                                    \
    _Pragma("unroll")                                                              \
    for (int j = 0; j < 4; j++) {                                                  \
        uint32_t ch = ach0 + j;                                                    \
        CPA16(a_ + ((ch * 16) ^ aswz), asrc + (K0) + ch * 8);                      \
    }                                                                              \
    uint32_t b_ = sB + (ST) * 16384 + kb * 256;                                    \
    const __half* wp = W2 + (size_t)((K0) + kb) * DIM_ + n0;                       \
    _Pragma("unroll")                                                              \
    for (int j = 0; j < 4; j++) {                                                  \
        uint32_t ch = bch0 + j;                                                    \
        CPA16(b_ + ((ch * 16) ^ bswz), wp + ch * 8);                               \
    }                                                                              \
    CPCOMMIT();                                                                    \
} while (0)

    F2_CPA(0, 0);
    F2_CPA(BKH, 1);

    for (int t = 0; t < NT2; t++) {
        int st = t % 3;
        if (t == NT2 - 1) CPWAIT0(); else CPWAIT1();   // tail: no younger group exists
        __syncthreads();
        if (t + 2 < NT2) F2_CPA((t + 2) * BKH, (t + 2) % 3);
        uint32_t aB = sA + st * 16384, bB = sB + st * 16384;
#pragma unroll
        for (int kk = 0; kk < 4; kk++) {
            int ko = kk << 4;
            unsigned a0[4], a1[4], bf[8][2];
            LDSM(a0[0], a0[1], a0[2], a0[3], a_addr(aB, wm, ko, lane));
            LDSM(a1[0], a1[1], a1[2], a1[3], a_addr(aB, wm + 16, ko, lane));
            LDSMT(bf[0][0], bf[0][1], bf[1][0], bf[1][1], b_addr(bB, wn,      ko, lane, 256));
            LDSMT(bf[2][0], bf[2][1], bf[3][0], bf[3][1], b_addr(bB, wn + 16, ko, lane, 256));
            LDSMT(bf[4][0], bf[4][1], bf[5][0], bf[5][1], b_addr(bB, wn + 32, ko, lane, 256));
            LDSMT(bf[6][0], bf[6][1], bf[7][0], bf[7][1], b_addr(bB, wn + 48, ko, lane, 256));
#pragma unroll
            for (int ni = 0; ni < 8; ni++) {
                mma16(c[0][ni], a0, bf[ni]);
                mma16(c[1][ni], a1, bf[ni]);
            }
        }
    }

    // epilogue: weighted scatter-add
#pragma unroll
    for (int mi = 0; mi < 2; mi++) {
#pragma unroll
        for (int rr = 0; rr < 2; rr++) {
            int m = m0 + wm + (mi << 4) + r + (rr << 3);
            if (m < cnt) {
                int tk = g_tok[e * NTOK + m];
                float wgt = g_wt[e * NTOK + m];
                float* orow = out + (size_t)tk * DIM_;
#pragma unroll
                for (int ni = 0; ni < 8; ni++) {
                    int col = n0 + wn + (ni << 3) + (q << 1);
                    atomicAdd(&orow[col],     wgt * c[mi][ni][(rr << 1)]);
                    atomicAdd(&orow[col + 1], wgt * c[mi][ni][(rr << 1) + 1]);
                }
            }
        }
    }
}

// ---------------- launch ----------------
extern "C" void kernel_launch(void* const* d_in, const int* in_sizes, int n_in,
                              void* d_out, int out_size) {
    const float* x  = (const float*)d_in[0];
    const float* Wg = (const float*)d_in[1];
    const float* w1 = (const float*)d_in[2];
    const float* w3 = (const float*)d_in[3];
    const float* w2 = (const float*)d_in[4];
    float* out = (float*)d_out;
    (void)in_sizes; (void)n_in;

    static int attr_done = 0;
    if (!attr_done) {
        cudaFuncSetAttribute(ffn1_kernel, cudaFuncAttributeMaxDynamicSharedMemorySize, 98304);
        cudaFuncSetAttribute(ffn2_kernel, cudaFuncAttributeMaxDynamicSharedMemorySize, 98304);
        attr_done = 1;
    }

    cudaMemsetAsync(out, 0, (size_t)out_size * sizeof(float), 0);
    zero_cnt_kernel<<<1, 32>>>();
    cvt_w_kernel<<<(int)(WSZ * NEXP / (256 * 8)), 256>>>(w1, 0);
    cvt_w_kernel<<<(int)(WSZ * NEXP / (256 * 8)), 256>>>(w3, W3OFF);
    gate_kernel<<<NTOK, 128>>>(x, Wg);
    ffn1_kernel<<<dim3(NTOK / 128, HID_ / 64, NEXP), 256, 98304>>>(w2);
    ffn2_kernel<<<dim3(NTOK / 128, DIM_ / 128, NEXP), 256, 98304>>>(out);
}